// round 12
// baseline (speedup 1.0000x reference)
#include <cuda_runtime.h>
#include <cuda_fp16.h>
#include <cstdint>

// Problem constants (fixed by the dataset)
#define BB 4
#define N1 2048
#define N2 2048
#define FF 256
#define NEG_ALPHA 0.2f

// Scratch (static __device__ — no allocations allowed)
__device__ float g_v1[FF];
__device__ float g_v2[FF];
__device__ float g_s1[BB * N2];
__device__ float g_t2[BB * N2];
__device__ float g_e1[BB * N2];
__device__ float g_p1[BB * N2];
__device__ __half g_wh[(size_t)BB * N1 * N2];   // attention weights (fp16), 32MB
__device__ __half g_wth[(size_t)BB * FF * N2];  // word transposed (fp16): [b][f][k], 4MB

__device__ __forceinline__ uint32_t smem_u32(const void* p) {
    uint32_t a;
    asm("{ .reg .u64 t; cvta.to.shared.u64 t, %1; cvt.u32.u64 %0, t; }"
        : "=r"(a) : "l"(p));
    return a;
}

// ---------------------------------------------------------------------------
// K1: v1 = W1 @ w3[:256], v2 = W2 @ w3[256:]
// ---------------------------------------------------------------------------
__global__ void k1_vec(const float* __restrict__ W1, const float* __restrict__ W2,
                       const float* __restrict__ w3) {
    int gw   = blockIdx.x * 8 + (threadIdx.x >> 5);
    int lane = threadIdx.x & 31;
    int which = gw >> 8;
    int f     = gw & 255;
    const float* W = which ? W2 : W1;
    const float* w = w3 + (which ? FF : 0);
    float s = 0.f;
    #pragma unroll
    for (int k = 0; k < 8; k++)
        s += W[f * FF + lane + 32 * k] * w[lane + 32 * k];
    #pragma unroll
    for (int o = 16; o > 0; o >>= 1)
        s += __shfl_down_sync(0xffffffffu, s, o);
    if (lane == 0) {
        if (which) g_v2[f] = s; else g_v1[f] = s;
    }
}

// ---------------------------------------------------------------------------
// K2: per node j: s1, t2, exp(s1), exp(.2 s1)
// ---------------------------------------------------------------------------
__global__ void k2_proj(const float* __restrict__ word) {
    int row  = blockIdx.x * 8 + (threadIdx.x >> 5);
    int lane = threadIdx.x & 31;
    const float* wr = word + (size_t)row * FF;
    float s = 0.f, t = 0.f;
    #pragma unroll
    for (int k = 0; k < 8; k++) {
        float x = wr[lane + 32 * k];
        s += x * g_v1[lane + 32 * k];
        t += x * g_v2[lane + 32 * k];
    }
    #pragma unroll
    for (int o = 16; o > 0; o >>= 1) {
        s += __shfl_down_sync(0xffffffffu, s, o);
        t += __shfl_down_sync(0xffffffffu, t, o);
    }
    if (lane == 0) {
        g_s1[row] = s;
        g_t2[row] = t;
        g_e1[row] = __expf(s);
        g_p1[row] = __expf(NEG_ALPHA * s);
    }
}

// ---------------------------------------------------------------------------
// K2T: g_wth[b][f][k] = half(word[b][k][f])  (tiled transpose)
// ---------------------------------------------------------------------------
__global__ void k2t_transpose(const float* __restrict__ word) {
    __shared__ float t[32][33];
    int b  = blockIdx.z;
    int k0 = blockIdx.x * 32;
    int f0 = blockIdx.y * 32;
    int r = threadIdx.x >> 5;     // 0..7
    int c = threadIdx.x & 31;
    #pragma unroll
    for (int it = 0; it < 4; it++) {
        int k = k0 + r + 8 * it;
        t[r + 8 * it][c] = word[((size_t)(b * N2 + k)) * FF + f0 + c];
    }
    __syncthreads();
    #pragma unroll
    for (int it = 0; it < 4; it++) {
        int f = f0 + r + 8 * it;
        g_wth[((size_t)(b * FF + f)) * N2 + k0 + c] = __float2half_rn(t[c][r + 8 * it]);
    }
}

// ---------------------------------------------------------------------------
// K3: 8 rows per block; broadcast column vectors staged in SMEM (32KB) once
//     per block and reused across the 8 rows. Low register pressure.
// ---------------------------------------------------------------------------
#define R3 8
__global__ __launch_bounds__(256)
void k3_stats(const float* __restrict__ adj) {
    __shared__ float sv_t2[N2];   // 8KB
    __shared__ float sv_s1[N2];   // 8KB
    __shared__ float sv_e1[N2];   // 8KB
    __shared__ float sv_p1[N2];   // 8KB
    __shared__ float sh1[8], sh2[8], sh3[8];

    int row0 = blockIdx.x * R3;        // all R3 rows share batch b (2048 % 8 == 0)
    int b    = row0 >> 11;
    int base = b << 11;
    int tid  = threadIdx.x;
    int w = tid >> 5, ln = tid & 31;
    int col0 = tid * 8;

    // cooperative fill of the broadcast vectors (2 float4 per array per thread)
    {
        int i0 = tid * 4;
        int i1 = i0 + 1024;
        *(float4*)(sv_t2 + i0) = *(const float4*)(g_t2 + base + i0);
        *(float4*)(sv_t2 + i1) = *(const float4*)(g_t2 + base + i1);
        *(float4*)(sv_s1 + i0) = *(const float4*)(g_s1 + base + i0);
        *(float4*)(sv_s1 + i1) = *(const float4*)(g_s1 + base + i1);
        *(float4*)(sv_e1 + i0) = *(const float4*)(g_e1 + base + i0);
        *(float4*)(sv_e1 + i1) = *(const float4*)(g_e1 + base + i1);
        *(float4*)(sv_p1 + i0) = *(const float4*)(g_p1 + base + i0);
        *(float4*)(sv_p1 + i1) = *(const float4*)(g_p1 + base + i1);
    }
    __syncthreads();

    const float* ap = adj  + (size_t)row0 * N2 + col0;
    __half*      wp = g_wh + (size_t)row0 * N2 + col0;

    for (int r = 0; r < R3; r++, ap += N2, wp += N2) {
        float a[8];
        *(float4*)(a)     = *(const float4*)(ap);
        *(float4*)(a + 4) = *(const float4*)(ap + 4);

        float deg, sr;
        {
            float4 t0 = *(float4*)(sv_t2 + col0);
            float4 t1 = *(float4*)(sv_t2 + col0 + 4);
            deg = (((a[0] + a[1]) + (a[2] + a[3])) + ((a[4] + a[5]) + (a[6] + a[7])));
            sr  = a[0] * t0.x + a[1] * t0.y + a[2] * t0.z + a[3] * t0.w
                + a[4] * t1.x + a[5] * t1.y + a[6] * t1.z + a[7] * t1.w;
        }
        #pragma unroll
        for (int o = 16; o > 0; o >>= 1) {
            deg += __shfl_down_sync(0xffffffffu, deg, o);
            sr  += __shfl_down_sync(0xffffffffu, sr,  o);
        }
        if (ln == 0) { sh1[w] = deg; sh2[w] = sr; }
        __syncthreads();

        float D = 0.f, S = 0.f;
        #pragma unroll
        for (int q = 0; q < 8; q++) { D += sh1[q]; S += sh2[q]; }
        float s2 = S / fmaxf(D, 1.0f);
        float E2 = __expf(s2);
        float P2 = __expf(NEG_ALPHA * s2);

        float e[8];
        float z = 0.f;
        {
            float4 sa = *(float4*)(sv_s1 + col0);
            float4 sb = *(float4*)(sv_s1 + col0 + 4);
            float4 ea = *(float4*)(sv_e1 + col0);
            float4 eb = *(float4*)(sv_e1 + col0 + 4);
            float4 pa = *(float4*)(sv_p1 + col0);
            float4 pb = *(float4*)(sv_p1 + col0 + 4);
            float svv[8] = {sa.x, sa.y, sa.z, sa.w, sb.x, sb.y, sb.z, sb.w};
            float evv[8] = {ea.x, ea.y, ea.z, ea.w, eb.x, eb.y, eb.z, eb.w};
            float pvv[8] = {pa.x, pa.y, pa.z, pa.w, pb.x, pb.y, pb.z, pb.w};
            #pragma unroll
            for (int k = 0; k < 8; k++) {
                float pre   = s2 + svv[k];
                float inner = (pre >= 0.f) ? E2 * evv[k] : P2 * pvv[k];
                e[k] = __expf(inner);
                z   += a[k] * e[k];
            }
        }
        #pragma unroll
        for (int o = 16; o > 0; o >>= 1) z += __shfl_down_sync(0xffffffffu, z, o);
        if (ln == 0) sh3[w] = z;
        __syncthreads();

        float Z = 0.f;
        #pragma unroll
        for (int q = 0; q < 8; q++) Z += sh3[q];
        float invZ = (D > 0.f) ? (1.0f / Z) : -1.0f;

        __half2 h[4];
        #pragma unroll
        for (int q = 0; q < 4; q++) {
            float w0 = (invZ < 0.f) ? (1.0f / 2048.0f)
                                    : (a[2 * q]     > 0.f ? e[2 * q]     * invZ : 0.f);
            float w1 = (invZ < 0.f) ? (1.0f / 2048.0f)
                                    : (a[2 * q + 1] > 0.f ? e[2 * q + 1] * invZ : 0.f);
            h[q] = __floats2half2_rn(w0, w1);
        }
        *(uint4*)(wp) = *(uint4*)h;
    }
}

// ---------------------------------------------------------------------------
// K4: edge = W @ word via HMMA mma.sync.m16n8k16 (fp16 in, fp32 accum).
//     BM=64 BN=128 BK=32(halfs), 256 threads (8 warps, 2x4),
//     3-stage cp.async pipeline, 3 CTAs/SM.
// ---------------------------------------------------------------------------
#define BM 64
#define BN 128
#define BK 32
#define ASTH 40   // A smem row stride (halfs); 20 words -> banks 20g+tg distinct
#define BSTH 40   // B smem row stride (halfs)
#define NKI (N2 / BK)
#define STAGES 3

__device__ __forceinline__ void mma_f16(float c[4], const uint32_t a[4],
                                        uint32_t b0, uint32_t b1) {
    asm volatile(
        "mma.sync.aligned.m16n8k16.row.col.f32.f16.f16.f32 "
        "{%0,%1,%2,%3},{%4,%5,%6,%7},{%8,%9},{%0,%1,%2,%3};"
        : "+f"(c[0]), "+f"(c[1]), "+f"(c[2]), "+f"(c[3])
        : "r"(a[0]), "r"(a[1]), "r"(a[2]), "r"(a[3]), "r"(b0), "r"(b1));
}

__device__ __forceinline__ void cp16(uint32_t smem_dst, const void* gptr) {
    asm volatile("cp.async.cg.shared.global [%0], [%1], 16;"
                 :: "r"(smem_dst), "l"(gptr));
}

__global__ __launch_bounds__(256, 3)
void k4_gemm(float* __restrict__ out) {
    __shared__ __align__(16) __half As[STAGES][BM * ASTH];   // 3 x 5120 B
    __shared__ __align__(16) __half Bs[STAGES][BN * BSTH];   // 3 x 10240 B

    int b   = blockIdx.z;
    int i0  = blockIdx.y * BM;
    int f0  = blockIdx.x * BN;
    int tid = threadIdx.x;
    int wid = tid >> 5, lane = tid & 31;
    int g = lane >> 2, tg = lane & 3;
    int wm = (wid & 1) * 32;    // 2 warp rows
    int wn = (wid >> 1) * 32;   // 4 warp cols

    float acc[2][4][4];
    #pragma unroll
    for (int t = 0; t < 2; t++)
        #pragma unroll
        for (int u = 0; u < 4; u++)
            #pragma unroll
            for (int q = 0; q < 4; q++) acc[t][u][q] = 0.f;

    // fill mapping: thread t -> row t>>2, 8-half chunk (t&3)*8
    int arow = tid >> 2, ac8 = (tid & 3) * 8;
    const __half* aG = g_wh + ((size_t)(b * N1 + i0 + arow)) * N2 + ac8;
    const __half* bG = g_wth + ((size_t)(b * FF + f0 + arow)) * N2 + ac8;

    uint32_t dA  = smem_u32(As) + (arow * ASTH + ac8) * 2;
    uint32_t dB  = smem_u32(Bs) + (arow * BSTH + ac8) * 2;
    uint32_t dB2 = dB + 64 * BSTH * 2;

    #define FILL(stage, kt) do { \
        int _k0 = (kt) * BK; \
        cp16(dA  + (stage) * (BM * ASTH * 2), aG + _k0); \
        cp16(dB  + (stage) * (BN * BSTH * 2), bG + _k0); \
        cp16(dB2 + (stage) * (BN * BSTH * 2), bG + (size_t)64 * N2 + _k0); \
        asm volatile("cp.async.commit_group;"); \
    } while (0)

    FILL(0, 0);
    FILL(1, 1);

    for (int kt = 0; kt < NKI; kt++) {
        asm volatile("cp.async.wait_group 1;");
        __syncthreads();

        if (kt + 2 < NKI) {
            int ns = (kt + 2) % STAGES;
            FILL(ns, kt + 2);
        } else {
            asm volatile("cp.async.commit_group;");
        }

        int cur = kt % STAGES;
        const uint32_t* As32 = (const uint32_t*)As[cur];
        const uint32_t* Bs32 = (const uint32_t*)Bs[cur];

        // ---- 2 k-steps of 16 ----
        #pragma unroll
        for (int s = 0; s < 2; s++) {
            int kw = s * 8 + tg;   // word offset within row (k/2)
            uint32_t afr[2][4];
            #pragma unroll
            for (int t = 0; t < 2; t++) {
                int mb = wm + t * 16;
                afr[t][0] = As32[(mb + g)     * (ASTH / 2) + kw];
                afr[t][1] = As32[(mb + g + 8) * (ASTH / 2) + kw];
                afr[t][2] = As32[(mb + g)     * (ASTH / 2) + kw + 4];
                afr[t][3] = As32[(mb + g + 8) * (ASTH / 2) + kw + 4];
            }
            #pragma unroll
            for (int u = 0; u < 4; u++) {
                int n = wn + u * 8 + g;
                uint32_t b0 = Bs32[n * (BSTH / 2) + kw];
                uint32_t b1 = Bs32[n * (BSTH / 2) + kw + 4];
                #pragma unroll
                for (int t = 0; t < 2; t++)
                    mma_f16(acc[t][u], afr[t], b0, b1);
            }
        }
    }

    // ---- epilogue: float2 stores ----
    #pragma unroll
    for (int t = 0; t < 2; t++) {
        int rowg = i0 + wm + t * 16 + g;
        #pragma unroll
        for (int u = 0; u < 4; u++) {
            int col = f0 + wn + u * 8 + 2 * tg;
            float2 v0 = make_float2(acc[t][u][0], acc[t][u][1]);
            float2 v1 = make_float2(acc[t][u][2], acc[t][u][3]);
            *(float2*)(out + ((size_t)(b * N1 + rowg)) * FF + col)     = v0;
            *(float2*)(out + ((size_t)(b * N1 + rowg + 8)) * FF + col) = v1;
        }
    }
}

// ---------------------------------------------------------------------------
extern "C" void kernel_launch(void* const* d_in, const int* in_sizes, int n_in,
                              void* d_out, int out_size) {
    (void)out_size;
    const float *word = nullptr, *adj = nullptr, *W1 = nullptr, *W2 = nullptr, *w3 = nullptr;
    for (int i = 0; i < n_in; i++) {
        int sz = in_sizes[i];
        const float* p = (const float*)d_in[i];
        if      (sz == BB * N1 * N2) adj = p;
        else if (sz == BB * N2 * FF) word = p;
        else if (sz == 2 * FF)       w3 = p;
        else if (sz == FF * FF)      { if (!W1) W1 = p; else W2 = p; }
    }
    float* out = (float*)d_out;

    k1_vec<<<64, 256>>>(W1, W2, w3);
    k2_proj<<<(BB * N2) / 8, 256>>>(word);
    k2t_transpose<<<dim3(N2 / 32, FF / 32, BB), 256>>>(word);
    k3_stats<<<(BB * N1) / R3, 256>>>(adj);
    k4_gemm<<<dim3(FF / BN, N1 / BM, BB), 256>>>(out);
}

// round 13
// speedup vs baseline: 1.2298x; 1.2298x over previous
#include <cuda_runtime.h>
#include <cuda_fp16.h>
#include <cstdint>

// Problem constants (fixed by the dataset)
#define BB 4
#define N1 2048
#define N2 2048
#define FF 256
#define NEG_ALPHA 0.2f

// Scratch (static __device__ — no allocations allowed)
__device__ float g_v1[FF];
__device__ float g_v2[FF];
__device__ float g_s1[BB * N2];
__device__ float g_t2[BB * N2];
__device__ __half g_wh[(size_t)BB * N1 * N2];   // attention weights (fp16), 32MB
__device__ __half g_wth[(size_t)BB * FF * N2];  // word transposed (fp16): [b][f][k], 4MB

__device__ __forceinline__ uint32_t smem_u32(const void* p) {
    uint32_t a;
    asm("{ .reg .u64 t; cvta.to.shared.u64 t, %1; cvt.u32.u64 %0, t; }"
        : "=r"(a) : "l"(p));
    return a;
}

// ---------------------------------------------------------------------------
// K1: v1 = W1 @ w3[:256], v2 = W2 @ w3[256:]
// ---------------------------------------------------------------------------
__global__ void k1_vec(const float* __restrict__ W1, const float* __restrict__ W2,
                       const float* __restrict__ w3) {
    int gw   = blockIdx.x * 8 + (threadIdx.x >> 5);
    int lane = threadIdx.x & 31;
    int which = gw >> 8;
    int f     = gw & 255;
    const float* W = which ? W2 : W1;
    const float* w = w3 + (which ? FF : 0);
    float s = 0.f;
    #pragma unroll
    for (int k = 0; k < 8; k++)
        s += W[f * FF + lane + 32 * k] * w[lane + 32 * k];
    #pragma unroll
    for (int o = 16; o > 0; o >>= 1)
        s += __shfl_down_sync(0xffffffffu, s, o);
    if (lane == 0) {
        if (which) g_v2[f] = s; else g_v1[f] = s;
    }
}

// ---------------------------------------------------------------------------
// K2: per node j: s1 = word_j·v1 ; t2 = word_j·v2
// ---------------------------------------------------------------------------
__global__ void k2_proj(const float* __restrict__ word) {
    int row  = blockIdx.x * 8 + (threadIdx.x >> 5);
    int lane = threadIdx.x & 31;
    const float* wr = word + (size_t)row * FF;
    float s = 0.f, t = 0.f;
    #pragma unroll
    for (int k = 0; k < 8; k++) {
        float x = wr[lane + 32 * k];
        s += x * g_v1[lane + 32 * k];
        t += x * g_v2[lane + 32 * k];
    }
    #pragma unroll
    for (int o = 16; o > 0; o >>= 1) {
        s += __shfl_down_sync(0xffffffffu, s, o);
        t += __shfl_down_sync(0xffffffffu, t, o);
    }
    if (lane == 0) {
        g_s1[row] = s;
        g_t2[row] = t;
    }
}

// ---------------------------------------------------------------------------
// K2T: g_wth[b][f][k] = half(word[b][k][f])  (tiled transpose)
// ---------------------------------------------------------------------------
__global__ void k2t_transpose(const float* __restrict__ word) {
    __shared__ float t[32][33];
    int b  = blockIdx.z;
    int k0 = blockIdx.x * 32;
    int f0 = blockIdx.y * 32;
    int r = threadIdx.x >> 5;     // 0..7
    int c = threadIdx.x & 31;
    #pragma unroll
    for (int it = 0; it < 4; it++) {
        int k = k0 + r + 8 * it;
        t[r + 8 * it][c] = word[((size_t)(b * N2 + k)) * FF + f0 + c];
    }
    __syncthreads();
    #pragma unroll
    for (int it = 0; it < 4; it++) {
        int f = f0 + r + 8 * it;
        g_wth[((size_t)(b * FF + f)) * N2 + k0 + c] = __float2half_rn(t[c][r + 8 * it]);
    }
}

// ---------------------------------------------------------------------------
// K3: one 256-thread block per output row (b,i) — the R8 structure that
//     measured fastest. deg, s2 = (Σ adj·t2)/max(deg,1),
//     Z = Σ adj·exp(exp(lrelu(s2+s1_j))), write fp16 weight row.
//     e computed directly with 2 expf (no e1/p1 precomputed arrays).
// ---------------------------------------------------------------------------
__global__ __launch_bounds__(256)
void k3_stats(const float* __restrict__ adj) {
    __shared__ float shd[8], shs[8];
    __shared__ float bc[4];
    int row = blockIdx.x;
    int b   = row >> 11;
    int tid = threadIdx.x;
    const float* ar = adj + (size_t)row * N2;
    int base = b << 11;

    float a[8];
    float deg = 0.f, sr = 0.f;
    #pragma unroll
    for (int k = 0; k < 8; k++) {
        a[k] = ar[tid + 256 * k];
        deg += a[k];
        sr  += a[k] * g_t2[base + tid + 256 * k];
    }
    #pragma unroll
    for (int o = 16; o > 0; o >>= 1) {
        deg += __shfl_down_sync(0xffffffffu, deg, o);
        sr  += __shfl_down_sync(0xffffffffu, sr,  o);
    }
    int w = tid >> 5, ln = tid & 31;
    if (ln == 0) { shd[w] = deg; shs[w] = sr; }
    __syncthreads();
    if (tid == 0) {
        float D = 0.f, S = 0.f;
        #pragma unroll
        for (int q = 0; q < 8; q++) { D += shd[q]; S += shs[q]; }
        bc[0] = S / fmaxf(D, 1.0f);
        bc[1] = D;
    }
    __syncthreads();
    float s2 = bc[0], D = bc[1];

    float e[8];
    float z = 0.f;
    #pragma unroll
    for (int k = 0; k < 8; k++) {
        float pre = s2 + g_s1[base + tid + 256 * k];
        float lr  = pre > 0.f ? pre : NEG_ALPHA * pre;
        e[k] = __expf(__expf(lr));
        z   += a[k] * e[k];
    }
    #pragma unroll
    for (int o = 16; o > 0; o >>= 1) z += __shfl_down_sync(0xffffffffu, z, o);
    if (ln == 0) shd[w] = z;
    __syncthreads();
    if (tid == 0) {
        float Z = 0.f;
        #pragma unroll
        for (int q = 0; q < 8; q++) Z += shd[q];
        bc[0] = (D > 0.f) ? (1.0f / Z) : -1.0f;
    }
    __syncthreads();
    float invZ = bc[0];

    __half* wr = g_wh + (size_t)row * N2;
    #pragma unroll
    for (int k = 0; k < 8; k++) {
        float wv = (invZ < 0.f) ? (1.0f / 2048.0f)
                                : (a[k] > 0.f ? e[k] * invZ : 0.f);
        wr[tid + 256 * k] = __float2half_rn(wv);
    }
}

// ---------------------------------------------------------------------------
// K4: edge = W @ word via HMMA mma.sync.m16n8k16 (fp16 in, fp32 accum).
//     BM=64 BN=128 BK=32(halfs), 256 threads (8 warps, 2x4),
//     3-stage cp.async pipeline, 3 CTAs/SM.
// ---------------------------------------------------------------------------
#define BM 64
#define BN 128
#define BK 32
#define ASTH 40   // A smem row stride (halfs); 20 words -> banks 20g+tg distinct
#define BSTH 40   // B smem row stride (halfs)
#define NKI (N2 / BK)
#define STAGES 3

__device__ __forceinline__ void mma_f16(float c[4], const uint32_t a[4],
                                        uint32_t b0, uint32_t b1) {
    asm volatile(
        "mma.sync.aligned.m16n8k16.row.col.f32.f16.f16.f32 "
        "{%0,%1,%2,%3},{%4,%5,%6,%7},{%8,%9},{%0,%1,%2,%3};"
        : "+f"(c[0]), "+f"(c[1]), "+f"(c[2]), "+f"(c[3])
        : "r"(a[0]), "r"(a[1]), "r"(a[2]), "r"(a[3]), "r"(b0), "r"(b1));
}

__device__ __forceinline__ void cp16(uint32_t smem_dst, const void* gptr) {
    asm volatile("cp.async.cg.shared.global [%0], [%1], 16;"
                 :: "r"(smem_dst), "l"(gptr));
}

__global__ __launch_bounds__(256, 3)
void k4_gemm(float* __restrict__ out) {
    __shared__ __align__(16) __half As[STAGES][BM * ASTH];   // 3 x 5120 B
    __shared__ __align__(16) __half Bs[STAGES][BN * BSTH];   // 3 x 10240 B

    int b   = blockIdx.z;
    int i0  = blockIdx.y * BM;
    int f0  = blockIdx.x * BN;
    int tid = threadIdx.x;
    int wid = tid >> 5, lane = tid & 31;
    int g = lane >> 2, tg = lane & 3;
    int wm = (wid & 1) * 32;    // 2 warp rows
    int wn = (wid >> 1) * 32;   // 4 warp cols

    float acc[2][4][4];
    #pragma unroll
    for (int t = 0; t < 2; t++)
        #pragma unroll
        for (int u = 0; u < 4; u++)
            #pragma unroll
            for (int q = 0; q < 4; q++) acc[t][u][q] = 0.f;

    // fill mapping: thread t -> row t>>2, 8-half chunk (t&3)*8
    int arow = tid >> 2, ac8 = (tid & 3) * 8;
    const __half* aG = g_wh + ((size_t)(b * N1 + i0 + arow)) * N2 + ac8;
    const __half* bG = g_wth + ((size_t)(b * FF + f0 + arow)) * N2 + ac8;

    uint32_t dA  = smem_u32(As) + (arow * ASTH + ac8) * 2;
    uint32_t dB  = smem_u32(Bs) + (arow * BSTH + ac8) * 2;
    uint32_t dB2 = dB + 64 * BSTH * 2;

    #define FILL(stage, kt) do { \
        int _k0 = (kt) * BK; \
        cp16(dA  + (stage) * (BM * ASTH * 2), aG + _k0); \
        cp16(dB  + (stage) * (BN * BSTH * 2), bG + _k0); \
        cp16(dB2 + (stage) * (BN * BSTH * 2), bG + (size_t)64 * N2 + _k0); \
        asm volatile("cp.async.commit_group;"); \
    } while (0)

    FILL(0, 0);
    FILL(1, 1);

    for (int kt = 0; kt < NKI; kt++) {
        asm volatile("cp.async.wait_group 1;");
        __syncthreads();

        if (kt + 2 < NKI) {
            int ns = (kt + 2) % STAGES;
            FILL(ns, kt + 2);
        } else {
            asm volatile("cp.async.commit_group;");
        }

        int cur = kt % STAGES;
        const uint32_t* As32 = (const uint32_t*)As[cur];
        const uint32_t* Bs32 = (const uint32_t*)Bs[cur];

        // ---- 2 k-steps of 16 ----
        #pragma unroll
        for (int s = 0; s < 2; s++) {
            int kw = s * 8 + tg;   // word offset within row (k/2)
            uint32_t afr[2][4];
            #pragma unroll
            for (int t = 0; t < 2; t++) {
                int mb = wm + t * 16;
                afr[t][0] = As32[(mb + g)     * (ASTH / 2) + kw];
                afr[t][1] = As32[(mb + g + 8) * (ASTH / 2) + kw];
                afr[t][2] = As32[(mb + g)     * (ASTH / 2) + kw + 4];
                afr[t][3] = As32[(mb + g + 8) * (ASTH / 2) + kw + 4];
            }
            #pragma unroll
            for (int u = 0; u < 4; u++) {
                int n = wn + u * 8 + g;
                uint32_t b0 = Bs32[n * (BSTH / 2) + kw];
                uint32_t b1 = Bs32[n * (BSTH / 2) + kw + 4];
                #pragma unroll
                for (int t = 0; t < 2; t++)
                    mma_f16(acc[t][u], afr[t], b0, b1);
            }
        }
    }

    // ---- epilogue: float2 stores ----
    #pragma unroll
    for (int t = 0; t < 2; t++) {
        int rowg = i0 + wm + t * 16 + g;
        #pragma unroll
        for (int u = 0; u < 4; u++) {
            int col = f0 + wn + u * 8 + 2 * tg;
            float2 v0 = make_float2(acc[t][u][0], acc[t][u][1]);
            float2 v1 = make_float2(acc[t][u][2], acc[t][u][3]);
            *(float2*)(out + ((size_t)(b * N1 + rowg)) * FF + col)     = v0;
            *(float2*)(out + ((size_t)(b * N1 + rowg + 8)) * FF + col) = v1;
        }
    }
}

// ---------------------------------------------------------------------------
extern "C" void kernel_launch(void* const* d_in, const int* in_sizes, int n_in,
                              void* d_out, int out_size) {
    (void)out_size;
    const float *word = nullptr, *adj = nullptr, *W1 = nullptr, *W2 = nullptr, *w3 = nullptr;
    for (int i = 0; i < n_in; i++) {
        int sz = in_sizes[i];
        const float* p = (const float*)d_in[i];
        if      (sz == BB * N1 * N2) adj = p;
        else if (sz == BB * N2 * FF) word = p;
        else if (sz == 2 * FF)       w3 = p;
        else if (sz == FF * FF)      { if (!W1) W1 = p; else W2 = p; }
    }
    float* out = (float*)d_out;

    k1_vec<<<64, 256>>>(W1, W2, w3);
    k2_proj<<<(BB * N2) / 8, 256>>>(word);
    k2t_transpose<<<dim3(N2 / 32, FF / 32, BB), 256>>>(word);
    k3_stats<<<BB * N1, 256>>>(adj);
    k4_gemm<<<dim3(FF / BN, N1 / BM, BB), 256>>>(out);
}

// round 14
// speedup vs baseline: 1.4327x; 1.1650x over previous
#include <cuda_runtime.h>
#include <cuda_fp16.h>
#include <cstdint>

// Problem constants (fixed by the dataset)
#define BB 4
#define N1 2048
#define N2 2048
#define FF 256
#define NEG_ALPHA 0.2f

// Scratch (static __device__ — no allocations allowed)
__device__ float g_v1[FF];
__device__ float g_v2[FF];
__device__ float g_s1[BB * N2];
__device__ float g_t2[BB * N2];
__device__ __half g_wh[(size_t)BB * N1 * N2];   // attention weights (fp16), 32MB
__device__ __half g_wth[(size_t)BB * FF * N2];  // word transposed (fp16): [b][f][k], 4MB

__device__ __forceinline__ uint32_t smem_u32(const void* p) {
    uint32_t a;
    asm("{ .reg .u64 t; cvta.to.shared.u64 t, %1; cvt.u32.u64 %0, t; }"
        : "=r"(a) : "l"(p));
    return a;
}

// ---------------------------------------------------------------------------
// K1: v1 = W1 @ w3[:256], v2 = W2 @ w3[256:]
// ---------------------------------------------------------------------------
__global__ void k1_vec(const float* __restrict__ W1, const float* __restrict__ W2,
                       const float* __restrict__ w3) {
    int gw   = blockIdx.x * 8 + (threadIdx.x >> 5);
    int lane = threadIdx.x & 31;
    int which = gw >> 8;
    int f     = gw & 255;
    const float* W = which ? W2 : W1;
    const float* w = w3 + (which ? FF : 0);
    float s = 0.f;
    #pragma unroll
    for (int k = 0; k < 8; k++)
        s += W[f * FF + lane + 32 * k] * w[lane + 32 * k];
    #pragma unroll
    for (int o = 16; o > 0; o >>= 1)
        s += __shfl_down_sync(0xffffffffu, s, o);
    if (lane == 0) {
        if (which) g_v2[f] = s; else g_v1[f] = s;
    }
}

// ---------------------------------------------------------------------------
// K2: per node j: s1 = word_j·v1 ; t2 = word_j·v2
// ---------------------------------------------------------------------------
__global__ void k2_proj(const float* __restrict__ word) {
    int row  = blockIdx.x * 8 + (threadIdx.x >> 5);
    int lane = threadIdx.x & 31;
    const float* wr = word + (size_t)row * FF;
    float s = 0.f, t = 0.f;
    #pragma unroll
    for (int k = 0; k < 8; k++) {
        float x = wr[lane + 32 * k];
        s += x * g_v1[lane + 32 * k];
        t += x * g_v2[lane + 32 * k];
    }
    #pragma unroll
    for (int o = 16; o > 0; o >>= 1) {
        s += __shfl_down_sync(0xffffffffu, s, o);
        t += __shfl_down_sync(0xffffffffu, t, o);
    }
    if (lane == 0) {
        g_s1[row] = s;
        g_t2[row] = t;
    }
}

// ---------------------------------------------------------------------------
// K2T: g_wth[b][f][k] = half(word[b][k][f])  (tiled transpose)
// ---------------------------------------------------------------------------
__global__ void k2t_transpose(const float* __restrict__ word) {
    __shared__ float t[32][33];
    int b  = blockIdx.z;
    int k0 = blockIdx.x * 32;
    int f0 = blockIdx.y * 32;
    int r = threadIdx.x >> 5;     // 0..7
    int c = threadIdx.x & 31;
    #pragma unroll
    for (int it = 0; it < 4; it++) {
        int k = k0 + r + 8 * it;
        t[r + 8 * it][c] = word[((size_t)(b * N2 + k)) * FF + f0 + c];
    }
    __syncthreads();
    #pragma unroll
    for (int it = 0; it < 4; it++) {
        int f = f0 + r + 8 * it;
        g_wth[((size_t)(b * FF + f)) * N2 + k0 + c] = __float2half_rn(t[c][r + 8 * it]);
    }
}

// ---------------------------------------------------------------------------
// K3: one 256-thread block per output row (b,i). deg, s2, Z, write fp16 row.
// ---------------------------------------------------------------------------
__global__ __launch_bounds__(256)
void k3_stats(const float* __restrict__ adj) {
    __shared__ float shd[8], shs[8];
    __shared__ float bc[4];
    int row = blockIdx.x;
    int b   = row >> 11;
    int tid = threadIdx.x;
    const float* ar = adj + (size_t)row * N2;
    int base = b << 11;

    float a[8];
    float deg = 0.f, sr = 0.f;
    #pragma unroll
    for (int k = 0; k < 8; k++) {
        a[k] = ar[tid + 256 * k];
        deg += a[k];
        sr  += a[k] * g_t2[base + tid + 256 * k];
    }
    #pragma unroll
    for (int o = 16; o > 0; o >>= 1) {
        deg += __shfl_down_sync(0xffffffffu, deg, o);
        sr  += __shfl_down_sync(0xffffffffu, sr,  o);
    }
    int w = tid >> 5, ln = tid & 31;
    if (ln == 0) { shd[w] = deg; shs[w] = sr; }
    __syncthreads();
    if (tid == 0) {
        float D = 0.f, S = 0.f;
        #pragma unroll
        for (int q = 0; q < 8; q++) { D += shd[q]; S += shs[q]; }
        bc[0] = S / fmaxf(D, 1.0f);
        bc[1] = D;
    }
    __syncthreads();
    float s2 = bc[0], D = bc[1];

    float e[8];
    float z = 0.f;
    #pragma unroll
    for (int k = 0; k < 8; k++) {
        float pre = s2 + g_s1[base + tid + 256 * k];
        float lr  = pre > 0.f ? pre : NEG_ALPHA * pre;
        e[k] = __expf(__expf(lr));
        z   += a[k] * e[k];
    }
    #pragma unroll
    for (int o = 16; o > 0; o >>= 1) z += __shfl_down_sync(0xffffffffu, z, o);
    if (ln == 0) shd[w] = z;
    __syncthreads();
    if (tid == 0) {
        float Z = 0.f;
        #pragma unroll
        for (int q = 0; q < 8; q++) Z += shd[q];
        bc[0] = (D > 0.f) ? (1.0f / Z) : -1.0f;
    }
    __syncthreads();
    float invZ = bc[0];

    __half* wr = g_wh + (size_t)row * N2;
    #pragma unroll
    for (int k = 0; k < 8; k++) {
        float wv = (invZ < 0.f) ? (1.0f / 2048.0f)
                                : (a[k] > 0.f ? e[k] * invZ : 0.f);
        wr[tid + 256 * k] = __float2half_rn(wv);
    }
}

// ---------------------------------------------------------------------------
// K4: edge = W @ word via HMMA mma.sync.m16n8k16 (fp16 in, fp32 accum).
//     BM=64 BN=128 BK=32(halfs), 256 threads (8 warps, 2x4),
//     3-stage cp.async pipeline, ldmatrix fragment loads, 3 CTAs/SM.
// ---------------------------------------------------------------------------
#define BM 64
#define BN 128
#define BK 32
#define ASTH 40   // A smem row stride (halfs) = 80B; ldmatrix rows hit distinct banks
#define BSTH 40   // B smem row stride (halfs)
#define NKI (N2 / BK)
#define STAGES 3

__device__ __forceinline__ void mma_f16(float c[4], const uint32_t a[4],
                                        uint32_t b0, uint32_t b1) {
    asm volatile(
        "mma.sync.aligned.m16n8k16.row.col.f32.f16.f16.f32 "
        "{%0,%1,%2,%3},{%4,%5,%6,%7},{%8,%9},{%0,%1,%2,%3};"
        : "+f"(c[0]), "+f"(c[1]), "+f"(c[2]), "+f"(c[3])
        : "r"(a[0]), "r"(a[1]), "r"(a[2]), "r"(a[3]), "r"(b0), "r"(b1));
}

__device__ __forceinline__ void ldsm_x4(uint32_t& r0, uint32_t& r1,
                                        uint32_t& r2, uint32_t& r3, uint32_t addr) {
    asm volatile("ldmatrix.sync.aligned.m8n8.x4.shared.b16 {%0,%1,%2,%3}, [%4];"
                 : "=r"(r0), "=r"(r1), "=r"(r2), "=r"(r3) : "r"(addr));
}

__device__ __forceinline__ void cp16(uint32_t smem_dst, const void* gptr) {
    asm volatile("cp.async.cg.shared.global [%0], [%1], 16;"
                 :: "r"(smem_dst), "l"(gptr));
}

__global__ __launch_bounds__(256, 3)
void k4_gemm(float* __restrict__ out) {
    __shared__ __align__(16) __half As[STAGES][BM * ASTH];   // 3 x 5120 B
    __shared__ __align__(16) __half Bs[STAGES][BN * BSTH];   // 3 x 10240 B

    int b   = blockIdx.z;
    int i0  = blockIdx.y * BM;
    int f0  = blockIdx.x * BN;
    int tid = threadIdx.x;
    int wid = tid >> 5, lane = tid & 31;
    int g = lane >> 2, tg = lane & 3;
    int wm = (wid & 1) * 32;    // 2 warp rows
    int wn = (wid >> 1) * 32;   // 4 warp cols

    float acc[2][4][4];
    #pragma unroll
    for (int t = 0; t < 2; t++)
        #pragma unroll
        for (int u = 0; u < 4; u++)
            #pragma unroll
            for (int q = 0; q < 4; q++) acc[t][u][q] = 0.f;

    // fill mapping: thread t -> row t>>2, 8-half chunk (t&3)*8
    int arow = tid >> 2, ac8 = (tid & 3) * 8;
    const __half* aG = g_wh + ((size_t)(b * N1 + i0 + arow)) * N2 + ac8;
    const __half* bG = g_wth + ((size_t)(b * FF + f0 + arow)) * N2 + ac8;

    uint32_t baseA = smem_u32(As);
    uint32_t baseB = smem_u32(Bs);
    uint32_t dA  = baseA + (arow * ASTH + ac8) * 2;
    uint32_t dB  = baseB + (arow * BSTH + ac8) * 2;
    uint32_t dB2 = dB + 64 * BSTH * 2;

    // ldmatrix per-lane address components
    int aRow = lane & 15;                         // row within 16-row t-tile
    int aCol = (lane >> 4) * 8;                   // +8 halfs for k8-15 matrices
    int bRow = (lane & 7) + ((lane & 16) >> 1);   // +8 rows for second n-block
    int bCol = lane & 8;                          // +8 halfs for k8-15 matrices

    #define FILL(stage, kt) do { \
        int _k0 = (kt) * BK; \
        cp16(dA  + (stage) * (BM * ASTH * 2), aG + _k0); \
        cp16(dB  + (stage) * (BN * BSTH * 2), bG + _k0); \
        cp16(dB2 + (stage) * (BN * BSTH * 2), bG + (size_t)64 * N2 + _k0); \
        asm volatile("cp.async.commit_group;"); \
    } while (0)

    FILL(0, 0);
    FILL(1, 1);

    for (int kt = 0; kt < NKI; kt++) {
        asm volatile("cp.async.wait_group 1;");
        __syncthreads();

        if (kt + 2 < NKI) {
            int ns = (kt + 2) % STAGES;
            FILL(ns, kt + 2);
        } else {
            asm volatile("cp.async.commit_group;");
        }

        int cur = kt % STAGES;
        uint32_t sA = baseA + cur * (BM * ASTH * 2);
        uint32_t sB = baseB + cur * (BN * BSTH * 2);

        // ---- 2 k-steps of 16, ldmatrix fragment loads ----
        #pragma unroll
        for (int s = 0; s < 2; s++) {
            int kh = s * 16;   // half offset within row
            uint32_t afr[2][4];
            #pragma unroll
            for (int t = 0; t < 2; t++) {
                uint32_t addr = sA + ((wm + t * 16 + aRow) * ASTH + kh + aCol) * 2;
                ldsm_x4(afr[t][0], afr[t][1], afr[t][2], afr[t][3], addr);
            }
            #pragma unroll
            for (int up = 0; up < 2; up++) {
                uint32_t br0, br1, br2, br3;
                uint32_t addr = sB + ((wn + up * 16 + bRow) * BSTH + kh + bCol) * 2;
                ldsm_x4(br0, br1, br2, br3, addr);
                #pragma unroll
                for (int t = 0; t < 2; t++) {
                    mma_f16(acc[t][2 * up],     afr[t], br0, br1);
                    mma_f16(acc[t][2 * up + 1], afr[t], br2, br3);
                }
            }
        }
    }

    // ---- epilogue: float2 stores ----
    #pragma unroll
    for (int t = 0; t < 2; t++) {
        int rowg = i0 + wm + t * 16 + g;
        #pragma unroll
        for (int u = 0; u < 4; u++) {
            int col = f0 + wn + u * 8 + 2 * tg;
            float2 v0 = make_float2(acc[t][u][0], acc[t][u][1]);
            float2 v1 = make_float2(acc[t][u][2], acc[t][u][3]);
            *(float2*)(out + ((size_t)(b * N1 + rowg)) * FF + col)     = v0;
            *(float2*)(out + ((size_t)(b * N1 + rowg + 8)) * FF + col) = v1;
        }
    }
}

// ---------------------------------------------------------------------------
extern "C" void kernel_launch(void* const* d_in, const int* in_sizes, int n_in,
                              void* d_out, int out_size) {
    (void)out_size;
    const float *word = nullptr, *adj = nullptr, *W1 = nullptr, *W2 = nullptr, *w3 = nullptr;
    for (int i = 0; i < n_in; i++) {
        int sz = in_sizes[i];
        const float* p = (const float*)d_in[i];
        if      (sz == BB * N1 * N2) adj = p;
        else if (sz == BB * N2 * FF) word = p;
        else if (sz == 2 * FF)       w3 = p;
        else if (sz == FF * FF)      { if (!W1) W1 = p; else W2 = p; }
    }
    float* out = (float*)d_out;

    k1_vec<<<64, 256>>>(W1, W2, w3);
    k2_proj<<<(BB * N2) / 8, 256>>>(word);
    k2t_transpose<<<dim3(N2 / 32, FF / 32, BB), 256>>>(word);
    k3_stats<<<BB * N1, 256>>>(adj);
    k4_gemm<<<dim3(FF / BN, N1 / BM, BB), 256>>>(out);
}

// round 16
// speedup vs baseline: 1.4508x; 1.0126x over previous
#include <cuda_runtime.h>
#include <cuda_fp16.h>
#include <cstdint>

// Problem constants (fixed by the dataset)
#define BB 4
#define N1 2048
#define N2 2048
#define FF 256
#define NEG_ALPHA 0.2f

// Scratch (static __device__ — no allocations allowed)
__device__ float g_v1[FF];
__device__ float g_v2[FF];
__device__ float g_s1[BB * N2];
__device__ float g_t2[BB * N2];
__device__ __half g_wh[(size_t)BB * N1 * N2];   // attention weights (fp16), 32MB
__device__ __half g_wth[(size_t)BB * FF * N2];  // word transposed (fp16): [b][f][k], 4MB

__device__ __forceinline__ uint32_t smem_u32(const void* p) {
    uint32_t a;
    asm("{ .reg .u64 t; cvta.to.shared.u64 t, %1; cvt.u32.u64 %0, t; }"
        : "=r"(a) : "l"(p));
    return a;
}

// ---------------------------------------------------------------------------
// K1: v1 = W1 @ w3[:256], v2 = W2 @ w3[256:]
// ---------------------------------------------------------------------------
__global__ void k1_vec(const float* __restrict__ W1, const float* __restrict__ W2,
                       const float* __restrict__ w3) {
    int gw   = blockIdx.x * 8 + (threadIdx.x >> 5);
    int lane = threadIdx.x & 31;
    int which = gw >> 8;
    int f     = gw & 255;
    const float* W = which ? W2 : W1;
    const float* w = w3 + (which ? FF : 0);
    float s = 0.f;
    #pragma unroll
    for (int k = 0; k < 8; k++)
        s += W[f * FF + lane + 32 * k] * w[lane + 32 * k];
    #pragma unroll
    for (int o = 16; o > 0; o >>= 1)
        s += __shfl_down_sync(0xffffffffu, s, o);
    if (lane == 0) {
        if (which) g_v2[f] = s; else g_v1[f] = s;
    }
}

// ---------------------------------------------------------------------------
// K2: per node j: s1 = word_j·v1 ; t2 = word_j·v2
// ---------------------------------------------------------------------------
__global__ void k2_proj(const float* __restrict__ word) {
    int row  = blockIdx.x * 8 + (threadIdx.x >> 5);
    int lane = threadIdx.x & 31;
    const float* wr = word + (size_t)row * FF;
    float s = 0.f, t = 0.f;
    #pragma unroll
    for (int k = 0; k < 8; k++) {
        float x = wr[lane + 32 * k];
        s += x * g_v1[lane + 32 * k];
        t += x * g_v2[lane + 32 * k];
    }
    #pragma unroll
    for (int o = 16; o > 0; o >>= 1) {
        s += __shfl_down_sync(0xffffffffu, s, o);
        t += __shfl_down_sync(0xffffffffu, t, o);
    }
    if (lane == 0) {
        g_s1[row] = s;
        g_t2[row] = t;
    }
}

// ---------------------------------------------------------------------------
// K2T: g_wth[b][f][k] = half(word[b][k][f])  (tiled transpose)
// ---------------------------------------------------------------------------
__global__ void k2t_transpose(const float* __restrict__ word) {
    __shared__ float t[32][33];
    int b  = blockIdx.z;
    int k0 = blockIdx.x * 32;
    int f0 = blockIdx.y * 32;
    int r = threadIdx.x >> 5;     // 0..7
    int c = threadIdx.x & 31;
    #pragma unroll
    for (int it = 0; it < 4; it++) {
        int k = k0 + r + 8 * it;
        t[r + 8 * it][c] = word[((size_t)(b * N2 + k)) * FF + f0 + c];
    }
    __syncthreads();
    #pragma unroll
    for (int it = 0; it < 4; it++) {
        int f = f0 + r + 8 * it;
        g_wth[((size_t)(b * FF + f)) * N2 + k0 + c] = __float2half_rn(t[c][r + 8 * it]);
    }
}

// ---------------------------------------------------------------------------
// K3: one 256-thread block per output row (b,i). deg, s2, Z, write fp16 row.
//     Only 2 __syncthreads: leaders write partials, all threads sum them.
// ---------------------------------------------------------------------------
__global__ __launch_bounds__(256)
void k3_stats(const float* __restrict__ adj) {
    __shared__ float sh1[8], sh2[8], sh3[8];
    int row = blockIdx.x;
    int b   = row >> 11;
    int tid = threadIdx.x;
    const float* ar = adj + (size_t)row * N2;
    int base = b << 11;

    float a[8];
    float deg = 0.f, sr = 0.f;
    #pragma unroll
    for (int k = 0; k < 8; k++) {
        a[k] = ar[tid + 256 * k];
        deg += a[k];
        sr  += a[k] * g_t2[base + tid + 256 * k];
    }
    #pragma unroll
    for (int o = 16; o > 0; o >>= 1) {
        deg += __shfl_down_sync(0xffffffffu, deg, o);
        sr  += __shfl_down_sync(0xffffffffu, sr,  o);
    }
    int w = tid >> 5, ln = tid & 31;
    if (ln == 0) { sh1[w] = deg; sh2[w] = sr; }
    __syncthreads();

    float D = 0.f, S = 0.f;
    #pragma unroll
    for (int q = 0; q < 8; q++) { D += sh1[q]; S += sh2[q]; }
    float s2 = S / fmaxf(D, 1.0f);

    float e[8];
    float z = 0.f;
    #pragma unroll
    for (int k = 0; k < 8; k++) {
        float pre = s2 + g_s1[base + tid + 256 * k];
        float lr  = pre > 0.f ? pre : NEG_ALPHA * pre;
        e[k] = __expf(__expf(lr));
        z   += a[k] * e[k];
    }
    #pragma unroll
    for (int o = 16; o > 0; o >>= 1) z += __shfl_down_sync(0xffffffffu, z, o);
    if (ln == 0) sh3[w] = z;
    __syncthreads();

    float Z = 0.f;
    #pragma unroll
    for (int q = 0; q < 8; q++) Z += sh3[q];
    float invZ = (D > 0.f) ? (1.0f / Z) : -1.0f;

    __half* wr = g_wh + (size_t)row * N2;
    #pragma unroll
    for (int k = 0; k < 8; k++) {
        float wv = (invZ < 0.f) ? (1.0f / 2048.0f)
                                : (a[k] > 0.f ? e[k] * invZ : 0.f);
        wr[tid + 256 * k] = __float2half_rn(wv);
    }
}

// ---------------------------------------------------------------------------
// K4: edge = W @ word via HMMA mma.sync.m16n8k16 (fp16 in, fp32 accum).
//     BM=64 BN=128 BK=32(halfs), 256 threads (8 warps, 2x4),
//     3-stage cp.async pipeline, ldmatrix fragment loads, 3 CTAs/SM.
//     Static smem = 3*(5120+10240) = 45KB  (< 48KB limit — checked!)
// ---------------------------------------------------------------------------
#define BM 64
#define BN 128
#define BK 32
#define ASTH 40   // A smem row stride (halfs) = 80B; ldmatrix rows hit distinct banks
#define BSTH 40   // B smem row stride (halfs)
#define NKI (N2 / BK)
#define STAGES 3

__device__ __forceinline__ void mma_f16(float c[4], const uint32_t a[4],
                                        uint32_t b0, uint32_t b1) {
    asm volatile(
        "mma.sync.aligned.m16n8k16.row.col.f32.f16.f16.f32 "
        "{%0,%1,%2,%3},{%4,%5,%6,%7},{%8,%9},{%0,%1,%2,%3};"
        : "+f"(c[0]), "+f"(c[1]), "+f"(c[2]), "+f"(c[3])
        : "r"(a[0]), "r"(a[1]), "r"(a[2]), "r"(a[3]), "r"(b0), "r"(b1));
}

__device__ __forceinline__ void ldsm_x4(uint32_t& r0, uint32_t& r1,
                                        uint32_t& r2, uint32_t& r3, uint32_t addr) {
    asm volatile("ldmatrix.sync.aligned.m8n8.x4.shared.b16 {%0,%1,%2,%3}, [%4];"
                 : "=r"(r0), "=r"(r1), "=r"(r2), "=r"(r3) : "r"(addr));
}

__device__ __forceinline__ void cp16(uint32_t smem_dst, const void* gptr) {
    asm volatile("cp.async.cg.shared.global [%0], [%1], 16;"
                 :: "r"(smem_dst), "l"(gptr));
}

__global__ __launch_bounds__(256, 3)
void k4_gemm(float* __restrict__ out) {
    __shared__ __align__(16) __half As[STAGES][BM * ASTH];   // 3 x 5120 B
    __shared__ __align__(16) __half Bs[STAGES][BN * BSTH];   // 3 x 10240 B

    int b   = blockIdx.z;
    int i0  = blockIdx.y * BM;
    int f0  = blockIdx.x * BN;
    int tid = threadIdx.x;
    int wid = tid >> 5, lane = tid & 31;
    int g = lane >> 2, tg = lane & 3;
    int wm = (wid & 1) * 32;    // 2 warp rows
    int wn = (wid >> 1) * 32;   // 4 warp cols

    float acc[2][4][4];
    #pragma unroll
    for (int t = 0; t < 2; t++)
        #pragma unroll
        for (int u = 0; u < 4; u++)
            #pragma unroll
            for (int q = 0; q < 4; q++) acc[t][u][q] = 0.f;

    // fill mapping: thread t -> row t>>2, 8-half chunk (t&3)*8
    int arow = tid >> 2, ac8 = (tid & 3) * 8;
    const __half* aG = g_wh + ((size_t)(b * N1 + i0 + arow)) * N2 + ac8;
    const __half* bG = g_wth + ((size_t)(b * FF + f0 + arow)) * N2 + ac8;

    uint32_t baseA = smem_u32(As);
    uint32_t baseB = smem_u32(Bs);
    uint32_t dA  = baseA + (arow * ASTH + ac8) * 2;
    uint32_t dB  = baseB + (arow * BSTH + ac8) * 2;
    uint32_t dB2 = dB + 64 * BSTH * 2;

    // ldmatrix per-lane address components
    int aRow = lane & 15;                         // row within 16-row t-tile
    int aCol = (lane >> 4) * 8;                   // +8 halfs for k8-15 matrices
    int bRow = (lane & 7) + ((lane & 16) >> 1);   // +8 rows for second n-block
    int bCol = lane & 8;                          // +8 halfs for k8-15 matrices

    #define FILL(stage, kt) do { \
        int _k0 = (kt) * BK; \
        cp16(dA  + (stage) * (BM * ASTH * 2), aG + _k0); \
        cp16(dB  + (stage) * (BN * BSTH * 2), bG + _k0); \
        cp16(dB2 + (stage) * (BN * BSTH * 2), bG + (size_t)64 * N2 + _k0); \
        asm volatile("cp.async.commit_group;"); \
    } while (0)

    FILL(0, 0);
    FILL(1, 1);

    for (int kt = 0; kt < NKI; kt++) {
        asm volatile("cp.async.wait_group 1;");
        __syncthreads();

        if (kt + 2 < NKI) {
            int ns = (kt + 2) % STAGES;
            FILL(ns, kt + 2);
        } else {
            asm volatile("cp.async.commit_group;");
        }

        int cur = kt % STAGES;
        uint32_t sA = baseA + cur * (BM * ASTH * 2);
        uint32_t sB = baseB + cur * (BN * BSTH * 2);

        // ---- 2 k-steps of 16, ldmatrix fragment loads ----
        #pragma unroll
        for (int s = 0; s < 2; s++) {
            int kh = s * 16;   // half offset within row
            uint32_t afr[2][4];
            #pragma unroll
            for (int t = 0; t < 2; t++) {
                uint32_t addr = sA + ((wm + t * 16 + aRow) * ASTH + kh + aCol) * 2;
                ldsm_x4(afr[t][0], afr[t][1], afr[t][2], afr[t][3], addr);
            }
            #pragma unroll
            for (int up = 0; up < 2; up++) {
                uint32_t br0, br1, br2, br3;
                uint32_t addr = sB + ((wn + up * 16 + bRow) * BSTH + kh + bCol) * 2;
                ldsm_x4(br0, br1, br2, br3, addr);
                #pragma unroll
                for (int t = 0; t < 2; t++) {
                    mma_f16(acc[t][2 * up],     afr[t], br0, br1);
                    mma_f16(acc[t][2 * up + 1], afr[t], br2, br3);
                }
            }
        }
    }

    // ---- epilogue: float2 stores ----
    #pragma unroll
    for (int t = 0; t < 2; t++) {
        int rowg = i0 + wm + t * 16 + g;
        #pragma unroll
        for (int u = 0; u < 4; u++) {
            int col = f0 + wn + u * 8 + 2 * tg;
            float2 v0 = make_float2(acc[t][u][0], acc[t][u][1]);
            float2 v1 = make_float2(acc[t][u][2], acc[t][u][3]);
            *(float2*)(out + ((size_t)(b * N1 + rowg)) * FF + col)     = v0;
            *(float2*)(out + ((size_t)(b * N1 + rowg + 8)) * FF + col) = v1;
        }
    }
}

// ---------------------------------------------------------------------------
extern "C" void kernel_launch(void* const* d_in, const int* in_sizes, int n_in,
                              void* d_out, int out_size) {
    (void)out_size;
    const float *word = nullptr, *adj = nullptr, *W1 = nullptr, *W2 = nullptr, *w3 = nullptr;
    for (int i = 0; i < n_in; i++) {
        int sz = in_sizes[i];
        const float* p = (const float*)d_in[i];
        if      (sz == BB * N1 * N2) adj = p;
        else if (sz == BB * N2 * FF) word = p;
        else if (sz == 2 * FF)       w3 = p;
        else if (sz == FF * FF)      { if (!W1) W1 = p; else W2 = p; }
    }
    float* out = (float*)d_out;

    k1_vec<<<64, 256>>>(W1, W2, w3);
    k2_proj<<<(BB * N2) / 8, 256>>>(word);
    k2t_transpose<<<dim3(N2 / 32, FF / 32, BB), 256>>>(word);
    k3_stats<<<BB * N1, 256>>>(adj);
    k4_gemm<<<dim3(FF / BN, N1 / BM, BB), 256>>>(out);
}